// round 2
// baseline (speedup 1.0000x reference)
#include <cuda_runtime.h>
#include <cuda_bf16.h>

#define Hh 96
#define Ww 96
#define HW (Hh*Ww)
#define NS 8

// Scratch (no allocations allowed): masks, squared column-distances, per-(sample,dir) max bits.
__device__ unsigned char d_mask[2 * NS * HW];
__device__ float         d_g2[2 * NS * HW];
__device__ int           d_dirMax[2 * NS];

// ---------------------------------------------------------------------------
// Kernel 1: threshold masks + vertical (column) 1D distance pass.
// One thread per (sample, mask, column) = 8*2*96 = 1536 threads.
// Forward+backward sweeps kept fully in registers (tmp[96], static indices).
// Stores g^2 (squared nearest-row distance in pixels), 1e18 sentinel if column
// (so far) has no points — the backward/forward min makes it INF only when the
// whole column is empty.
// Also zeroes d_dirMax (threads 0..15) so every graph replay is deterministic.
// ---------------------------------------------------------------------------
__global__ void k_columns(const float* __restrict__ predict,
                          const float* __restrict__ target) {
    int idx = blockIdx.x * blockDim.x + threadIdx.x;
    if (idx < 2 * NS) d_dirMax[idx] = 0;
    if (idx >= 2 * NS * Ww) return;

    int n   = idx / (2 * Ww);
    int rem = idx % (2 * Ww);
    int m   = rem / Ww;     // 0 = predict (A), 1 = target (B)
    int j   = rem % Ww;

    const float* img = (m == 0) ? predict : target;
    const float* col = img + n * HW + j;
    unsigned char* mk = d_mask + (n * 2 + m) * HW + j;
    float*         g2 = d_g2   + (n * 2 + m) * HW + j;

    int tmp[Hh];
    int up = 1 << 14;
    #pragma unroll
    for (int i = 0; i < Hh; i++) {
        // jnp.round(x) > 0.5 for x in [0,1): true iff x > 0.5 (0.5 rounds to 0)
        bool b = col[i * Ww] > 0.5f;
        mk[i * Ww] = b ? (unsigned char)1 : (unsigned char)0;
        up = b ? 0 : (up + 1);
        tmp[i] = up;
    }
    int down = 1 << 14;
    #pragma unroll
    for (int i = Hh - 1; i >= 0; i--) {
        down = (tmp[i] == 0) ? 0 : (down + 1);
        int gm = (tmp[i] < down) ? tmp[i] : down;
        // valid distances are <= 95; anything >= Hh means empty column
        g2[i * Ww] = (gm >= Hh) ? 1e18f : (float)(gm * gm);
    }
}

// ---------------------------------------------------------------------------
// Kernel 2: horizontal (row) pass of the separable EDT + masked max reduce.
// Block = (row i, direction d, sample n); 96 threads (one per column j).
//   d2[i][j] = min_{j'} ( g2_tgt[i][j'] + (j-j')^2 )
// direction 0: src = A\B, tgt = B;  direction 1: src = B\A, tgt = A.
// Empty-target sentinel: m2 > 1e17  ->  directed distance contribution = 1e9
// (matches the reference's BIG for an empty target set).
// ---------------------------------------------------------------------------
__global__ void k_rows() {
    int i = blockIdx.x;
    int d = blockIdx.y;
    int n = blockIdx.z;
    int j = threadIdx.x;

    __shared__ float s[Ww];
    __shared__ float wmax[3];

    int tgtm = (d == 0) ? 1 : 0;
    s[j] = d_g2[(n * 2 + tgtm) * HW + i * Ww + j];
    __syncthreads();

    float t  = (float)j;
    float m2 = 3e38f;
    #pragma unroll
    for (int jp = 0; jp < Ww; jp++) {
        float dj = t - (float)jp;
        m2 = fminf(m2, fmaf(dj, dj, s[jp]));
    }

    unsigned char sa = d_mask[(n * 2 + 0) * HW + i * Ww + j];
    unsigned char sb = d_mask[(n * 2 + 1) * HW + i * Ww + j];
    bool srcp = (d == 0) ? (sa && !sb) : (sb && !sa);

    float local = 0.0f;
    if (srcp)
        local = (m2 > 1e17f) ? 1e9f : sqrtf(m2) * (1.0f / (float)Hh);

    // warp max reduce (3 warps) then block combine + one atomic per block
    #pragma unroll
    for (int off = 16; off > 0; off >>= 1)
        local = fmaxf(local, __shfl_xor_sync(0xffffffffu, local, off));
    if ((j & 31) == 0) wmax[j >> 5] = local;
    __syncthreads();
    if (j == 0) {
        float v = fmaxf(fmaxf(wmax[0], wmax[1]), wmax[2]);
        // nonnegative floats: int-bit compare preserves order
        atomicMax(&d_dirMax[n * 2 + d], __float_as_int(v));
    }
}

// ---------------------------------------------------------------------------
// Kernel 3: combine 16 directed maxima -> mean Hausdorff over 8 samples.
// ---------------------------------------------------------------------------
__global__ void k_final(float* __restrict__ out) {
    float acc = 0.0f;
    #pragma unroll
    for (int n = 0; n < NS; n++) {
        float da = __int_as_float(d_dirMax[2 * n + 0]);
        float db = __int_as_float(d_dirMax[2 * n + 1]);
        acc += fmaxf(da, db);
    }
    out[0] = acc * (1.0f / (float)NS);
}

extern "C" void kernel_launch(void* const* d_in, const int* in_sizes, int n_in,
                              void* d_out, int out_size) {
    const float* predict = (const float*)d_in[0];
    const float* target  = (const float*)d_in[1];
    float* out = (float*)d_out;

    // 1536 threads total for the column pass
    k_columns<<<12, 128>>>(predict, target);

    dim3 grid(Hh, 2, NS);   // (row, direction, sample)
    k_rows<<<grid, Ww>>>();

    k_final<<<1, 1>>>(out);
}

// round 3
// speedup vs baseline: 1.3434x; 1.3434x over previous
#include <cuda_runtime.h>
#include <cuda_bf16.h>

#define Hh 96
#define Ww 96
#define HW (Hh*Ww)
#define NS 8

// Scratch (allocation-free): masks, squared column distances, per-(sample,dir)
// max bits, and a completion counter for the fused final reduction.
__device__ unsigned char d_mask[2 * NS * HW];
__device__ float         d_g2[2 * NS * HW];
__device__ int           d_dirMax[2 * NS];
__device__ unsigned int  d_count;

// ---------------------------------------------------------------------------
// Kernel 1: threshold + vertical (column) 1D distance pass.
// Block = (sample, mask) pair, 96 threads = one per column. Forward-sweep
// "up" distances are clamped to 127 and packed 4-per-uint32 with STATIC
// indices (full unroll) -> tmpw[24] stays in registers (~24 regs, no spill),
// unlike the R2 version whose int tmp[96] hit 254 regs and spilled to local.
// Loads are coalesced (thread j reads img[i*96+j]); all 96 loads independent.
// Block 0 also zeroes d_dirMax / d_count for deterministic graph replay.
// ---------------------------------------------------------------------------
__global__ void k_columns(const float* __restrict__ predict,
                          const float* __restrict__ target) {
    int b = blockIdx.x;        // 0..15
    int n = b >> 1;
    int m = b & 1;             // 0 = predict (A), 1 = target (B)
    int j = threadIdx.x;       // 0..95

    if (b == 0) {
        if (j < 2 * NS) d_dirMax[j] = 0;
        if (j == 2 * NS) d_count = 0;
    }

    const float* col = ((m == 0) ? predict : target) + n * HW + j;
    unsigned char* mk = d_mask + (n * 2 + m) * HW + j;
    float*         g2 = d_g2   + (n * 2 + m) * HW + j;

    unsigned tmpw[24];
    int up = 127;
    #pragma unroll
    for (int i = 0; i < Hh; i++) {
        // jnp.round(x) > 0.5 for x in [0,1): true iff x > 0.5 (0.5 rounds to 0)
        bool bset = col[i * Ww] > 0.5f;
        mk[i * Ww] = bset ? (unsigned char)1 : (unsigned char)0;
        up = bset ? 0 : ((up < 127) ? up + 1 : 127);
        if ((i & 3) == 0) tmpw[i >> 2] = (unsigned)up;
        else              tmpw[i >> 2] |= ((unsigned)up) << ((i & 3) * 8);
    }
    int down = 127;
    #pragma unroll
    for (int i = Hh - 1; i >= 0; i--) {
        int upv = (int)((tmpw[i >> 2] >> ((i & 3) * 8)) & 255u);
        down = (upv == 0) ? 0 : ((down < 127) ? down + 1 : 127);
        int gm = (upv < down) ? upv : down;
        // valid distances <= 95; >= Hh means the whole column is empty
        g2[i * Ww] = (gm >= Hh) ? 1e18f : (float)(gm * gm);
    }
}

// ---------------------------------------------------------------------------
// Kernel 2: horizontal pass of the separable EDT for BOTH masks at once,
// masked max reduce for both directions, and (last block) final mean.
// Block = (row i, sample n), 96 threads (one per column j).
//   distToB^2[j] = min_jp ( g2_B[i][jp] + (j-jp)^2 )   (and same for A)
// dj is shared between the two fmas -> 5 instrs per 2 outputs.
// Empty-target sentinel: m2 > 1e17 -> contribution 1e9 (reference BIG).
// Final reduction: atomic counter + threadfence; dirMax read back via
// atomics (L2) so no stale-L1 hazard.
// ---------------------------------------------------------------------------
__global__ void k_rows(float* __restrict__ out) {
    int i = blockIdx.x;
    int n = blockIdx.y;
    int j = threadIdx.x;

    __shared__ float sA[Ww];
    __shared__ float sB[Ww];
    __shared__ float wred[6];

    int base = i * Ww + j;
    sA[j] = d_g2[(n * 2 + 0) * HW + base];
    sB[j] = d_g2[(n * 2 + 1) * HW + base];
    unsigned char sa = d_mask[(n * 2 + 0) * HW + base];
    unsigned char sb = d_mask[(n * 2 + 1) * HW + base];
    __syncthreads();

    float t = (float)j;
    float mA2 = 3e38f, mB2 = 3e38f;
    #pragma unroll
    for (int jp = 0; jp < Ww; jp++) {
        float dj = t - (float)jp;
        mB2 = fminf(mB2, fmaf(dj, dj, sB[jp]));
        mA2 = fminf(mA2, fmaf(dj, dj, sA[jp]));
    }

    // direction 0: src = A\B, target set B;  direction 1: src = B\A, target A
    float l0 = (sa && !sb) ? ((mB2 > 1e17f) ? 1e9f : sqrtf(mB2) * (1.0f / 96.0f)) : 0.0f;
    float l1 = (!sa && sb) ? ((mA2 > 1e17f) ? 1e9f : sqrtf(mA2) * (1.0f / 96.0f)) : 0.0f;

    #pragma unroll
    for (int off = 16; off > 0; off >>= 1) {
        l0 = fmaxf(l0, __shfl_xor_sync(0xffffffffu, l0, off));
        l1 = fmaxf(l1, __shfl_xor_sync(0xffffffffu, l1, off));
    }
    if ((j & 31) == 0) { wred[j >> 5] = l0; wred[3 + (j >> 5)] = l1; }
    __syncthreads();

    if (j == 0) {
        float v0 = fmaxf(fmaxf(wred[0], wred[1]), wred[2]);
        float v1 = fmaxf(fmaxf(wred[3], wred[4]), wred[5]);
        // nonnegative floats: int-bit compare preserves order
        atomicMax(&d_dirMax[n * 2 + 0], __float_as_int(v0));
        atomicMax(&d_dirMax[n * 2 + 1], __float_as_int(v1));
        __threadfence();
        unsigned done = atomicAdd(&d_count, 1u);
        if (done == (unsigned)(Hh * NS - 1)) {
            float acc = 0.0f;
            #pragma unroll
            for (int k = 0; k < NS; k++) {
                float da = __int_as_float(atomicAdd(&d_dirMax[2 * k + 0], 0));
                float db = __int_as_float(atomicAdd(&d_dirMax[2 * k + 1], 0));
                acc += fmaxf(da, db);
            }
            out[0] = acc * (1.0f / (float)NS);
        }
    }
}

extern "C" void kernel_launch(void* const* d_in, const int* in_sizes, int n_in,
                              void* d_out, int out_size) {
    const float* predict = (const float*)d_in[0];
    const float* target  = (const float*)d_in[1];
    float* out = (float*)d_out;

    k_columns<<<16, 96>>>(predict, target);

    dim3 grid(Hh, NS);      // (row, sample)
    k_rows<<<grid, Ww>>>(out);
}

// round 5
// speedup vs baseline: 1.5581x; 1.1599x over previous
#include <cuda_runtime.h>
#include <cuda_bf16.h>

#define Hh 96
#define Ww 96
#define HW (Hh*Ww)
#define NS 8
#define RPB 4                      // rows per k_rows block
#define NBLK ((Hh/RPB)*NS)         // 192 k_rows blocks

// Scratch (allocation-free). Mask is implicit: g2 == 0.0f  <=>  pixel in mask.
__device__ float        d_g2[2 * NS * HW];
__device__ int          d_dirMax[2 * NS];
__device__ unsigned int d_count;

// ---------------------------------------------------------------------------
// Kernel 1: threshold + vertical (column) 1D distance pass.
// Block = (sample, mask) image, 96 threads = one per column. Forward "up"
// distances clamped to 127 and packed 4-per-uint32 with static indices
// (tmpw[24] stays in registers). Loads coalesced (thread j reads [i*96+j]).
// g2 == 0 exactly at mask pixels (distance 0 to itself) -> no mask array.
// Block 0 zeroes d_dirMax / d_count for deterministic graph replay.
// ---------------------------------------------------------------------------
__global__ void k_columns(const float* __restrict__ predict,
                          const float* __restrict__ target) {
    int b = blockIdx.x;        // 0..15
    int n = b >> 1;
    int m = b & 1;             // 0 = predict (A), 1 = target (B)
    int j = threadIdx.x;       // 0..95

    if (b == 0) {
        if (j < 2 * NS) d_dirMax[j] = 0;
        if (j == 2 * NS) d_count = 0;
    }

    const float* col = ((m == 0) ? predict : target) + n * HW + j;
    float*        g2 = d_g2 + (n * 2 + m) * HW + j;

    unsigned tmpw[24];
    int up = 127;
    #pragma unroll
    for (int i = 0; i < Hh; i++) {
        // jnp.round(x) > 0.5 for x in [0,1): true iff x > 0.5
        bool bset = col[i * Ww] > 0.5f;
        up = bset ? 0 : ((up < 127) ? up + 1 : 127);
        if ((i & 3) == 0) tmpw[i >> 2] = (unsigned)up;
        else              tmpw[i >> 2] |= ((unsigned)up) << ((i & 3) * 8);
    }
    int down = 127;
    #pragma unroll
    for (int i = Hh - 1; i >= 0; i--) {
        int upv = (int)((tmpw[i >> 2] >> ((i & 3) * 8)) & 255u);
        down = (upv == 0) ? 0 : ((down < 127) ? down + 1 : 127);
        int gm = (upv < down) ? upv : down;
        // valid distances <= 95; >= Hh means whole column empty
        g2[i * Ww] = (gm >= Hh) ? 1e18f : (float)(gm * gm);
    }
}

// ---------------------------------------------------------------------------
// Kernel 2: horizontal EDT with EARLY-EXIT outward scan + reductions + final.
// Block = (4 rows, sample), 384 threads. Each thread is one pixel (i,j).
// Source sets A\B and B\A are mutually exclusive -> each thread scans at most
// one target array. m2 starts at g2_tgt[j] (d=0); scanning d=1.. stops once
// d^2 >= m2 (no farther column can improve). Random ~50%-dense masks
// terminate in ~2-3 iters. Shared rows padded with 96x 1e18 guards per side
// -> no bounds branches in the scan.
// Empty target: m2 stays 1e18 -> directed distance 1e9 (reference BIG).
// Last finished block computes the final mean (counter + threadfence;
// dirMax read back via atomics to bypass stale L1).
// ---------------------------------------------------------------------------
__global__ void k_rows(float* __restrict__ out) {
    int n  = blockIdx.y;
    int ri = threadIdx.x / Ww;            // 0..3
    int j  = threadIdx.x % Ww;            // 0..95
    int i  = blockIdx.x * RPB + ri;

    __shared__ float sA[RPB][3 * Ww];     // [0,96) guard | [96,192) data | [192,288) guard
    __shared__ float sB[RPB][3 * Ww];
    __shared__ float wred0[12], wred1[12];

    sA[ri][j] = 1e18f;  sA[ri][2 * Ww + j] = 1e18f;
    sB[ri][j] = 1e18f;  sB[ri][2 * Ww + j] = 1e18f;

    int base = i * Ww + j;
    float gA = d_g2[(n * 2 + 0) * HW + base];
    float gB = d_g2[(n * 2 + 1) * HW + base];
    sA[ri][Ww + j] = gA;
    sB[ri][Ww + j] = gB;
    __syncthreads();

    bool sa = (gA == 0.0f);               // pixel in A
    bool sb = (gB == 0.0f);               // pixel in B

    float l0 = 0.0f, l1 = 0.0f;           // dir0: A\B vs B, dir1: B\A vs A
    if (sa != sb) {
        const float* sp = sa ? &sB[ri][Ww + j] : &sA[ri][Ww + j];
        float m2 = sp[0];
        #pragma unroll 1
        for (int d = 1; d < Ww; d++) {
            float dd = (float)(d * d);
            if (dd >= m2) break;
            m2 = fminf(m2, fminf(sp[-d], sp[d]) + dd);
        }
        float v = (m2 > 1e17f) ? 1e9f : sqrtf(m2) * (1.0f / 96.0f);
        l0 = sa ? v : 0.0f;
        l1 = sa ? 0.0f : v;
    }

    #pragma unroll
    for (int off = 16; off > 0; off >>= 1) {
        l0 = fmaxf(l0, __shfl_xor_sync(0xffffffffu, l0, off));
        l1 = fmaxf(l1, __shfl_xor_sync(0xffffffffu, l1, off));
    }
    if ((threadIdx.x & 31) == 0) {
        wred0[threadIdx.x >> 5] = l0;
        wred1[threadIdx.x >> 5] = l1;
    }
    __syncthreads();

    if (threadIdx.x == 0) {
        float v0 = wred0[0], v1 = wred1[0];
        #pragma unroll
        for (int k = 1; k < 12; k++) {
            v0 = fmaxf(v0, wred0[k]);
            v1 = fmaxf(v1, wred1[k]);
        }
        // nonnegative floats: int-bit compare preserves order
        atomicMax(&d_dirMax[n * 2 + 0], __float_as_int(v0));
        atomicMax(&d_dirMax[n * 2 + 1], __float_as_int(v1));
        __threadfence();
        unsigned done = atomicAdd(&d_count, 1u);
        if (done == (unsigned)(NBLK - 1)) {
            float acc = 0.0f;
            #pragma unroll
            for (int k = 0; k < NS; k++) {
                float da = __int_as_float(atomicAdd(&d_dirMax[2 * k + 0], 0));
                float db = __int_as_float(atomicAdd(&d_dirMax[2 * k + 1], 0));
                acc += fmaxf(da, db);
            }
            out[0] = acc * (1.0f / (float)NS);
        }
    }
}

extern "C" void kernel_launch(void* const* d_in, const int* in_sizes, int n_in,
                              void* d_out, int out_size) {
    const float* predict = (const float*)d_in[0];
    const float* target  = (const float*)d_in[1];
    float* out = (float*)d_out;

    k_columns<<<16, 96>>>(predict, target);

    dim3 grid(Hh / RPB, NS);   // (row-group, sample)
    k_rows<<<grid, RPB * Ww>>>(out);
}